// round 9
// baseline (speedup 1.0000x reference)
#include <cuda_runtime.h>
#include <cuda_bf16.h>
#include <cstdint>

typedef __nv_bfloat16 bf16;

// ---------------- problem dims ----------------
#define B_SZ   512
#define NSNP   20000
#define NGEN   5000
#define NPRO   3000
#define IN_COLS 28000     // NPRO + NGEN + NSNP
#define H1_N   1024
#define H2_N   256

// padded dims
#define NG_P   5120
#define NP_P   3072
#define K2_P   5024
#define K3_P   8192       // bridge K = 5120 + 3072
#define K4_P   3008
#define K5_P   6144       // fuse K = 3072 + 3072

// GEMM1 K-chunks (mult of 64; first small to cut serial mask exposure)
#define KC0 2496
#define KC1 5824
#define KC2 5824
#define KC3 5856

// ---------------- device scratch ----------------
__device__ bf16 g_snp[(size_t)B_SZ * NSNP];
__device__ bf16 g_gen[(size_t)B_SZ * K2_P];
__device__ bf16 g_pro[(size_t)B_SZ * K4_P];
__device__ bf16 g_Wm1[(size_t)NSNP * NG_P];   // [k][n]
__device__ bf16 g_Wm2[(size_t)K2_P * NP_P];
__device__ bf16 g_Wm3[(size_t)K3_P * NP_P];
__device__ bf16 g_Wm4[(size_t)K4_P * NP_P];
__device__ bf16 g_Wm5[(size_t)K5_P * H1_N];
__device__ bf16 g_Wm6[(size_t)H1_N * H2_N];
__device__ bf16 g_bridge[(size_t)B_SZ * K3_P];
__device__ bf16 g_fuse[(size_t)B_SZ * K5_P];
__device__ bf16 g_h1[(size_t)B_SZ * H1_N];
__device__ bf16 g_h2[(size_t)B_SZ * H2_N];
__device__ float g_accbuf[(size_t)8 * B_SZ * NG_P];   // split-K slice accumulators

// ---------------- helpers ----------------
__device__ __forceinline__ uint32_t smem_u32(const void* p) {
    return (uint32_t)__cvta_generic_to_shared(p);
}
__device__ __forceinline__ void cp_async16(uint32_t saddr, const void* gaddr) {
    asm volatile("cp.async.cg.shared.global [%0], [%1], 16;\n" ::"r"(saddr), "l"(gaddr));
}
__device__ __forceinline__ void cp_async_commit() {
    asm volatile("cp.async.commit_group;\n" ::: "memory");
}
template <int N>
__device__ __forceinline__ void cp_async_wait() {
    asm volatile("cp.async.wait_group %0;\n" ::"n"(N) : "memory");
}

// ---------------- mask + transpose + bf16 convert ----------------
__global__ void mask_transpose_kernel(const float* __restrict__ W, int ldw,
                                      const float* __restrict__ adj, int lda,
                                      bf16* __restrict__ out, int ldo,
                                      int K, int N) {
    __shared__ float sW[64][33];
    const int k0 = blockIdx.y * 32;
    const int n0 = blockIdx.x * 64;
    const int lin = threadIdx.y * 32 + threadIdx.x;

    {
        const int rn = lin >> 2, seg = (lin & 3) * 8;
        const int gn = n0 + rn;
        const int gk = k0 + seg;
        if (gn < N && gk + 7 < K) {
            const float4 v0 = *(const float4*)&W[(size_t)gn * ldw + gk];
            const float4 v1 = *(const float4*)&W[(size_t)gn * ldw + gk + 4];
            sW[rn][seg + 0] = v0.x; sW[rn][seg + 1] = v0.y;
            sW[rn][seg + 2] = v0.z; sW[rn][seg + 3] = v0.w;
            sW[rn][seg + 4] = v1.x; sW[rn][seg + 5] = v1.y;
            sW[rn][seg + 6] = v1.z; sW[rn][seg + 7] = v1.w;
        } else {
#pragma unroll
            for (int i = 0; i < 8; i++)
                sW[rn][seg + i] = (gn < N && gk + i < K) ? W[(size_t)gn * ldw + gk + i] : 0.f;
        }
    }
    __syncthreads();

    const int kl = lin >> 3;
    const int nb = (lin & 7) * 8;
    const int gk = k0 + kl;
    float v[8];
    if (gk < K && n0 + nb + 7 < N) {
        if (adj != nullptr) {
            const float4 a0 = *(const float4*)&adj[(size_t)gk * lda + n0 + nb];
            const float4 a1 = *(const float4*)&adj[(size_t)gk * lda + n0 + nb + 4];
            v[0] = sW[nb + 0][kl] * a0.x; v[1] = sW[nb + 1][kl] * a0.y;
            v[2] = sW[nb + 2][kl] * a0.z; v[3] = sW[nb + 3][kl] * a0.w;
            v[4] = sW[nb + 4][kl] * a1.x; v[5] = sW[nb + 5][kl] * a1.y;
            v[6] = sW[nb + 6][kl] * a1.z; v[7] = sW[nb + 7][kl] * a1.w;
        } else {
#pragma unroll
            for (int i = 0; i < 8; i++) v[i] = sW[nb + i][kl];
        }
    } else {
#pragma unroll
        for (int i = 0; i < 8; i++) {
            const int gn = n0 + nb + i;
            float x = 0.f;
            if (gk < K && gn < N) {
                x = sW[nb + i][kl];
                if (adj != nullptr) x *= adj[(size_t)gk * lda + gn];
            }
            v[i] = x;
        }
    }
    uint4 o;
    __nv_bfloat162 p;
    p = __floats2bfloat162_rn(v[0], v[1]); o.x = *(uint32_t*)&p;
    p = __floats2bfloat162_rn(v[2], v[3]); o.y = *(uint32_t*)&p;
    p = __floats2bfloat162_rn(v[4], v[5]); o.z = *(uint32_t*)&p;
    p = __floats2bfloat162_rn(v[6], v[7]); o.w = *(uint32_t*)&p;
    *(uint4*)&out[(size_t)gk * ldo + n0 + nb] = o;
}

// ---------------- fast activation convert (nvalid mult of 8) ----------------
// grid: (ceil(dst_ld/8/256), rows); vectorized float4x2 -> bf16x8.
__global__ void convert_pad_v_kernel(const float* __restrict__ src, int src_ld,
                                     bf16* __restrict__ dst, int dst_ld,
                                     int nvalid) {
    int c8 = blockIdx.x * blockDim.x + threadIdx.x;
    int col = c8 * 8;
    if (col >= dst_ld) return;
    int r = blockIdx.y;
    uint4 o;
    if (col < nvalid) {
        const float4 v0 = *(const float4*)&src[(size_t)r * src_ld + col];
        const float4 v1 = *(const float4*)&src[(size_t)r * src_ld + col + 4];
        __nv_bfloat162 p;
        p = __floats2bfloat162_rn(v0.x, v0.y); o.x = *(uint32_t*)&p;
        p = __floats2bfloat162_rn(v0.z, v0.w); o.y = *(uint32_t*)&p;
        p = __floats2bfloat162_rn(v1.x, v1.y); o.z = *(uint32_t*)&p;
        p = __floats2bfloat162_rn(v1.z, v1.w); o.w = *(uint32_t*)&p;
    } else {
        o = make_uint4(0, 0, 0, 0);
    }
    *(uint4*)&dst[(size_t)r * dst_ld + col] = o;
}

// ---------------- bf16 GEMM with split-K ----------------
// BM=128 BN=128 BK=32, 8 warps (2m x 4n), warp tile 64x32, 3-stage cp.async,
// 256 threads, 2 CTAs/SM (= 4 warps/SMSP).
#define BM 128
#define BN 128
#define BKG 32
#define AS_LD 40
#define BS_LD 136
#define STAGES 3
#define GEMM_SMEM (STAGES * (BM * AS_LD + BKG * BS_LD) * 2)

__global__ __launch_bounds__(256, 2) void gemm_bf16_kernel(
    const bf16* __restrict__ A, int lda,
    const bf16* __restrict__ Bw, int ldb,
    bf16* __restrict__ C, int ldc,
    const float* __restrict__ bias, int Nreal,
    int Kz, int Ktotal,
    float* __restrict__ Cacc, size_t accStride, int ldacc,
    int load_prev, int store_final) {
    extern __shared__ bf16 smem[];
    bf16* As = smem;                              // [STAGES][BM][AS_LD]
    bf16* Bs = smem + STAGES * BM * AS_LD;        // [STAGES][BKG][BS_LD]

    const int tid = threadIdx.x;
    const int bm = blockIdx.y * BM;
    const int bn = blockIdx.x * BN;
    const int warp = tid >> 5, lane = tid & 31;
    const int wm = (warp & 1) * 64;
    const int wn = (warp >> 1) * 32;

    // K-slice
    const int kbase = blockIdx.z * Kz;
    int Kthis = Ktotal - kbase;
    if (Kthis > Kz) Kthis = Kz;
    const bf16* Az = A + kbase;
    const bf16* Bz = Bw + (size_t)kbase * ldb;
    float* Cacc_z = Cacc + (size_t)blockIdx.z * accStride;

    float acc[4][4][4];
#pragma unroll
    for (int i = 0; i < 4; i++)
#pragma unroll
        for (int j = 0; j < 4; j++)
#pragma unroll
            for (int r = 0; r < 4; r++) acc[i][j][r] = 0.f;

    const int T = Kthis / BKG;
    // A tile 128x32 (512 x 16B): 256 thr -> 2 cps. row=tid>>1, seg=(tid&1)*16
    const int a_row = tid >> 1, a_seg = (tid & 1) * 16;
    // B tile 32x128 (512 x 16B): row=tid>>3, seg=(tid&7)*16
    const int b_row = tid >> 3, b_seg = (tid & 7) * 16;

#define LOAD_TILE(t, s)                                                              \
    {                                                                                \
        const int k0_ = (t) * BKG;                                                   \
        bf16* as_ = As + (s) * BM * AS_LD;                                           \
        bf16* bs_ = Bs + (s) * BKG * BS_LD;                                          \
        _Pragma("unroll") for (int p = 0; p < 2; p++) {                              \
            cp_async16(smem_u32(as_ + a_row * AS_LD + a_seg + p * 8),                \
                       Az + (size_t)(bm + a_row) * lda + k0_ + a_seg + p * 8);       \
        }                                                                            \
        _Pragma("unroll") for (int p = 0; p < 2; p++) {                              \
            cp_async16(smem_u32(bs_ + b_row * BS_LD + b_seg + p * 8),                \
                       Bz + (size_t)(k0_ + b_row) * ldb + bn + b_seg + p * 8);       \
        }                                                                            \
    }

    LOAD_TILE(0, 0);
    cp_async_commit();
    if (T > 1) LOAD_TILE(1, 1);
    cp_async_commit();

    for (int t = 0; t < T; ++t) {
        cp_async_wait<STAGES - 2>();
        __syncthreads();

        if (t + STAGES - 1 < T) LOAD_TILE(t + STAGES - 1, (t + STAGES - 1) % STAGES);
        cp_async_commit();

        const int s = t % STAGES;
        const bf16* as_ = As + s * BM * AS_LD;
        const bf16* bs_ = Bs + s * BKG * BS_LD;
#pragma unroll
        for (int kk = 0; kk < BKG; kk += 16) {
            uint32_t a[4][4];
#pragma unroll
            for (int im = 0; im < 4; im++) {
                uint32_t addr = smem_u32(as_ + (wm + im * 16 + (lane & 15)) * AS_LD + kk + (lane >> 4) * 8);
                asm volatile("ldmatrix.sync.aligned.m8n8.x4.shared.b16 {%0,%1,%2,%3}, [%4];"
                             : "=r"(a[im][0]), "=r"(a[im][1]), "=r"(a[im][2]), "=r"(a[im][3])
                             : "r"(addr));
            }
            uint32_t b[4][2];
#pragma unroll
            for (int ip = 0; ip < 2; ip++) {
                uint32_t r0, r1, r2, r3;
                uint32_t addr = smem_u32(bs_ + (kk + (lane & 15)) * BS_LD + wn + ip * 16 + (lane >> 4) * 8);
                asm volatile("ldmatrix.sync.aligned.m8n8.x4.trans.shared.b16 {%0,%1,%2,%3}, [%4];"
                             : "=r"(r0), "=r"(r1), "=r"(r2), "=r"(r3)
                             : "r"(addr));
                b[ip * 2][0] = r0; b[ip * 2][1] = r1;
                b[ip * 2 + 1][0] = r2; b[ip * 2 + 1][1] = r3;
            }
#pragma unroll
            for (int im = 0; im < 4; im++)
#pragma unroll
                for (int jn = 0; jn < 4; jn++) {
                    asm volatile(
                        "mma.sync.aligned.m16n8k16.row.col.f32.bf16.bf16.f32 "
                        "{%0,%1,%2,%3}, {%4,%5,%6,%7}, {%8,%9}, {%0,%1,%2,%3};"
                        : "+f"(acc[im][jn][0]), "+f"(acc[im][jn][1]),
                          "+f"(acc[im][jn][2]), "+f"(acc[im][jn][3])
                        : "r"(a[im][0]), "r"(a[im][1]), "r"(a[im][2]), "r"(a[im][3]),
                          "r"(b[jn][0]), "r"(b[jn][1]));
                }
        }
        __syncthreads();
    }

    if (!store_final) {
#pragma unroll
        for (int im = 0; im < 4; im++) {
            int r0 = bm + wm + im * 16 + (lane >> 2);
#pragma unroll
            for (int jn = 0; jn < 4; jn++) {
                int col = bn + wn + jn * 8 + (lane & 3) * 2;
                float2* p0 = (float2*)&Cacc_z[(size_t)r0 * ldacc + col];
                float2* p1 = (float2*)&Cacc_z[(size_t)(r0 + 8) * ldacc + col];
                float2 v0 = make_float2(acc[im][jn][0], acc[im][jn][1]);
                float2 v1 = make_float2(acc[im][jn][2], acc[im][jn][3]);
                if (load_prev) {
                    float2 o0 = *p0, o1 = *p1;
                    v0.x += o0.x; v0.y += o0.y;
                    v1.x += o1.x; v1.y += o1.y;
                }
                *p0 = v0; *p1 = v1;
            }
        }
    } else {
#pragma unroll
        for (int im = 0; im < 4; im++) {
            int r0 = bm + wm + im * 16 + (lane >> 2);
#pragma unroll
            for (int jn = 0; jn < 4; jn++) {
                int col = bn + wn + jn * 8 + (lane & 3) * 2;
                float bv0 = (col < Nreal) ? bias[col] : 0.f;
                float bv1 = (col + 1 < Nreal) ? bias[col + 1] : 0.f;
                float f0 = fmaxf(acc[im][jn][0] + bv0, 0.f);
                float f1 = fmaxf(acc[im][jn][1] + bv1, 0.f);
                float f2 = fmaxf(acc[im][jn][2] + bv0, 0.f);
                float f3 = fmaxf(acc[im][jn][3] + bv1, 0.f);
                *(__nv_bfloat162*)&C[(size_t)r0 * ldc + col] = __floats2bfloat162_rn(f0, f1);
                *(__nv_bfloat162*)&C[(size_t)(r0 + 8) * ldc + col] = __floats2bfloat162_rn(f2, f3);
            }
        }
    }
}

// ---------------- split-K reduce: C = relu(sum_s acc[s] + bias) -> bf16 ----------------
__global__ void reduce_bias_relu_kernel(const float* __restrict__ acc, size_t accStride, int S,
                                        const float* __restrict__ bias, int Nreal,
                                        bf16* __restrict__ C, int ldc, int Np) {
    int idx = blockIdx.x * blockDim.x + threadIdx.x;
    int half = Np >> 1;
    int total = B_SZ * half;
    if (idx >= total) return;
    int r = idx / half;
    int col = (idx - r * half) * 2;
    float s0 = 0.f, s1 = 0.f;
    const float* p = acc + (size_t)r * Np + col;
    for (int s = 0; s < S; s++) {
        float2 v = *(const float2*)(p + (size_t)s * accStride);
        s0 += v.x; s1 += v.y;
    }
    s0 += (col < Nreal) ? bias[col] : 0.f;
    s1 += (col + 1 < Nreal) ? bias[col + 1] : 0.f;
    *(__nv_bfloat162*)&C[(size_t)r * ldc + col] =
        __floats2bfloat162_rn(fmaxf(s0, 0.f), fmaxf(s1, 0.f));
}

// ---------------- final: y = sigmoid(h2 @ Wout + bout) ----------------
__global__ void final_kernel(const bf16* __restrict__ h2,
                             const float* __restrict__ Wout,
                             const float* __restrict__ bout,
                             float* __restrict__ y) {
    int row = blockIdx.x * 8 + (threadIdx.x >> 5);
    int lane = threadIdx.x & 31;
    float s = 0.f;
#pragma unroll
    for (int c = lane; c < H2_N; c += 32)
        s += __bfloat162float(h2[(size_t)row * H2_N + c]) * Wout[c];
#pragma unroll
    for (int o = 16; o; o >>= 1) s += __shfl_xor_sync(0xffffffffu, s, o);
    if (lane == 0) y[row] = 1.f / (1.f + expf(-(s + bout[0])));
}

// ---------------- launch ----------------
extern "C" void kernel_launch(void* const* d_in, const int* in_sizes, int n_in,
                              void* d_out, int out_size) {
    (void)in_sizes; (void)n_in; (void)out_size;
    const float* in_mat = (const float*)d_in[0];
    const float* adj_sg = (const float*)d_in[1];
    const float* adj_gp = (const float*)d_in[2];
    const float* adj_br = (const float*)d_in[3];
    const float* adj_pp = (const float*)d_in[4];
    const float* W_sg = (const float*)d_in[5];
    const float* b_sg = (const float*)d_in[6];
    const float* W_gp = (const float*)d_in[7];
    const float* b_gp = (const float*)d_in[8];
    const float* W_br = (const float*)d_in[9];
    const float* b_br = (const float*)d_in[10];
    const float* W_pp = (const float*)d_in[11];
    const float* b_pp = (const float*)d_in[12];
    const float* W_h1 = (const float*)d_in[13];
    const float* b_h1 = (const float*)d_in[14];
    const float* W_h2 = (const float*)d_in[15];
    const float* b_h2 = (const float*)d_in[16];
    const float* W_out = (const float*)d_in[17];
    const float* b_out = (const float*)d_in[18];
    float* y = (float*)d_out;

    bf16 *snp, *gen, *pro, *Wm1, *Wm2, *Wm3, *Wm4, *Wm5, *Wm6, *bridge, *fuse, *h1, *h2;
    float* accb;
    cudaGetSymbolAddress((void**)&snp, g_snp);
    cudaGetSymbolAddress((void**)&gen, g_gen);
    cudaGetSymbolAddress((void**)&pro, g_pro);
    cudaGetSymbolAddress((void**)&Wm1, g_Wm1);
    cudaGetSymbolAddress((void**)&Wm2, g_Wm2);
    cudaGetSymbolAddress((void**)&Wm3, g_Wm3);
    cudaGetSymbolAddress((void**)&Wm4, g_Wm4);
    cudaGetSymbolAddress((void**)&Wm5, g_Wm5);
    cudaGetSymbolAddress((void**)&Wm6, g_Wm6);
    cudaGetSymbolAddress((void**)&bridge, g_bridge);
    cudaGetSymbolAddress((void**)&fuse, g_fuse);
    cudaGetSymbolAddress((void**)&h1, g_h1);
    cudaGetSymbolAddress((void**)&h2, g_h2);
    cudaGetSymbolAddress((void**)&accb, g_accbuf);

    cudaFuncSetAttribute(gemm_bf16_kernel, cudaFuncAttributeMaxDynamicSharedMemorySize, GEMM_SMEM);

    static cudaStream_t s1 = nullptr;
    static cudaEvent_t ev_fork = nullptr, ev_join = nullptr;
    static cudaEvent_t ev_m1 = nullptr, ev_m2 = nullptr, ev_m3 = nullptr;
    if (s1 == nullptr) {
        cudaStreamCreateWithFlags(&s1, cudaStreamNonBlocking);
        cudaEventCreateWithFlags(&ev_fork, cudaEventDisableTiming);
        cudaEventCreateWithFlags(&ev_join, cudaEventDisableTiming);
        cudaEventCreateWithFlags(&ev_m1, cudaEventDisableTiming);
        cudaEventCreateWithFlags(&ev_m2, cudaEventDisableTiming);
        cudaEventCreateWithFlags(&ev_m3, cudaEventDisableTiming);
    }

    dim3 mt(32, 8);
    const int kc_off[4] = {0, KC0, KC0 + KC1, KC0 + KC1 + KC2};
    const int kc_len[4] = {KC0, KC1, KC2, KC3};
    const size_t ST1 = (size_t)B_SZ * NG_P;
    const size_t ST3 = (size_t)B_SZ * NP_P;
    const size_t ST5 = (size_t)B_SZ * H1_N;
    const size_t ST6 = (size_t)B_SZ * H2_N;

    // ======== s0: critical path start ========
    convert_pad_v_kernel<<<dim3((NSNP / 8 + 255) / 256, B_SZ), 256>>>(
        in_mat + NPRO + NGEN, IN_COLS, snp, NSNP, NSNP);
    mask_transpose_kernel<<<dim3(NG_P / 64, kc_len[0] / 32), mt>>>(
        W_sg + kc_off[0], NSNP, adj_sg + (size_t)kc_off[0] * NGEN, NGEN,
        Wm1 + (size_t)kc_off[0] * NG_P, NG_P, kc_len[0], NGEN);
    cudaEventRecord(ev_fork, 0);
    cudaStreamWaitEvent(s1, ev_fork, 0);

    // ======== s1: mask chunks 1-3 + side prep + GEMM2/GEMM4 ========
    mask_transpose_kernel<<<dim3(NG_P / 64, kc_len[1] / 32), mt, 0, s1>>>(
        W_sg + kc_off[1], NSNP, adj_sg + (size_t)kc_off[1] * NGEN, NGEN,
        Wm1 + (size_t)kc_off[1] * NG_P, NG_P, kc_len[1], NGEN);
    cudaEventRecord(ev_m1, s1);
    mask_transpose_kernel<<<dim3(NG_P / 64, kc_len[2] / 32), mt, 0, s1>>>(
        W_sg + kc_off[2], NSNP, adj_sg + (size_t)kc_off[2] * NGEN, NGEN,
        Wm1 + (size_t)kc_off[2] * NG_P, NG_P, kc_len[2], NGEN);
    cudaEventRecord(ev_m2, s1);
    mask_transpose_kernel<<<dim3(NG_P / 64, kc_len[3] / 32), mt, 0, s1>>>(
        W_sg + kc_off[3], NSNP, adj_sg + (size_t)kc_off[3] * NGEN, NGEN,
        Wm1 + (size_t)kc_off[3] * NG_P, NG_P, kc_len[3], NGEN);
    cudaEventRecord(ev_m3, s1);

    // ======== s0: GEMM1 chunks, split-K=2 each ========
    gemm_bf16_kernel<<<dim3(NG_P / BN, B_SZ / BM, 2), 256, GEMM_SMEM>>>(
        snp + kc_off[0], NSNP, Wm1 + (size_t)kc_off[0] * NG_P, NG_P,
        nullptr, 0, b_sg, NGEN, kc_len[0] / 2, kc_len[0], accb, ST1, NG_P, 0, 0);
    cudaStreamWaitEvent(0, ev_m1, 0);
    gemm_bf16_kernel<<<dim3(NG_P / BN, B_SZ / BM, 2), 256, GEMM_SMEM>>>(
        snp + kc_off[1], NSNP, Wm1 + (size_t)kc_off[1] * NG_P, NG_P,
        nullptr, 0, b_sg, NGEN, kc_len[1] / 2, kc_len[1], accb, ST1, NG_P, 1, 0);
    cudaStreamWaitEvent(0, ev_m2, 0);
    gemm_bf16_kernel<<<dim3(NG_P / BN, B_SZ / BM, 2), 256, GEMM_SMEM>>>(
        snp + kc_off[2], NSNP, Wm1 + (size_t)kc_off[2] * NG_P, NG_P,
        nullptr, 0, b_sg, NGEN, kc_len[2] / 2, kc_len[2], accb, ST1, NG_P, 1, 0);
    cudaStreamWaitEvent(0, ev_m3, 0);
    gemm_bf16_kernel<<<dim3(NG_P / BN, B_SZ / BM, 2), 256, GEMM_SMEM>>>(
        snp + kc_off[3], NSNP, Wm1 + (size_t)kc_off[3] * NG_P, NG_P,
        nullptr, 0, b_sg, NGEN, kc_len[3] / 2, kc_len[3], accb, ST1, NG_P, 1, 0);
    reduce_bias_relu_kernel<<<(B_SZ * NG_P / 2 + 255) / 256, 256>>>(
        accb, ST1, 2, b_sg, NGEN, bridge, K3_P, NG_P);

    // ======== s1 (continued): side prep + GEMM2/GEMM4 ========
    convert_pad_v_kernel<<<dim3((K2_P / 8 + 255) / 256, B_SZ), 256, 0, s1>>>(
        in_mat + NPRO, IN_COLS, gen, K2_P, NGEN);
    convert_pad_v_kernel<<<dim3((K4_P / 8 + 255) / 256, B_SZ), 256, 0, s1>>>(
        in_mat, IN_COLS, pro, K4_P, NPRO);
    mask_transpose_kernel<<<dim3(NP_P / 64, K2_P / 32), mt, 0, s1>>>(W_gp, NGEN, adj_gp, NPRO, Wm2, NP_P, NGEN, NPRO);
    mask_transpose_kernel<<<dim3(NP_P / 64, NG_P / 32), mt, 0, s1>>>(W_br, NGEN + NPRO, adj_br, NPRO, Wm3, NP_P, NGEN, NPRO);
    mask_transpose_kernel<<<dim3(NP_P / 64, NP_P / 32), mt, 0, s1>>>(W_br + NGEN, NGEN + NPRO,
                                                                    adj_br + (size_t)NGEN * NPRO, NPRO,
                                                                    Wm3 + (size_t)NG_P * NP_P, NP_P, NPRO, NPRO);
    mask_transpose_kernel<<<dim3(NP_P / 64, K4_P / 32), mt, 0, s1>>>(W_pp, NPRO, adj_pp, NPRO, Wm4, NP_P, NPRO, NPRO);
    mask_transpose_kernel<<<dim3(H1_N / 64, NP_P / 32), mt, 0, s1>>>(W_h1, 2 * NPRO, nullptr, 0, Wm5, H1_N, NPRO, H1_N);
    mask_transpose_kernel<<<dim3(H1_N / 64, NP_P / 32), mt, 0, s1>>>(W_h1 + NPRO, 2 * NPRO, nullptr, 0,
                                                                    Wm5 + (size_t)NP_P * H1_N, H1_N, NPRO, H1_N);
    mask_transpose_kernel<<<dim3(H2_N / 64, H1_N / 32), mt, 0, s1>>>(W_h2, H1_N, nullptr, 0, Wm6, H2_N, H1_N, H2_N);
    gemm_bf16_kernel<<<dim3(NP_P / BN, B_SZ / BM, 1), 256, GEMM_SMEM, s1>>>(
        gen, K2_P, Wm2, NP_P, bridge + NG_P, K3_P, b_gp, NPRO, K2_P, K2_P, nullptr, 0, 0, 0, 1);
    gemm_bf16_kernel<<<dim3(NP_P / BN, B_SZ / BM, 1), 256, GEMM_SMEM, s1>>>(
        pro, K4_P, Wm4, NP_P, fuse + NP_P, K5_P, b_pp, NPRO, K4_P, K4_P, nullptr, 0, 0, 0, 1);
    cudaEventRecord(ev_join, s1);

    // ======== s0: join, dependent tail (split-K) ========
    cudaStreamWaitEvent(0, ev_join, 0);
    gemm_bf16_kernel<<<dim3(NP_P / BN, B_SZ / BM, 3), 256, GEMM_SMEM>>>(
        bridge, K3_P, Wm3, NP_P, nullptr, 0, b_br, NPRO, 2752, K3_P, accb, ST3, NP_P, 0, 0);
    reduce_bias_relu_kernel<<<(B_SZ * NP_P / 2 + 255) / 256, 256>>>(
        accb, ST3, 3, b_br, NPRO, fuse, K5_P, NP_P);
    gemm_bf16_kernel<<<dim3(H1_N / BN, B_SZ / BM, 8), 256, GEMM_SMEM>>>(
        fuse, K5_P, Wm5, H1_N, nullptr, 0, b_h1, H1_N, 768, K5_P, accb, ST5, H1_N, 0, 0);
    reduce_bias_relu_kernel<<<(B_SZ * H1_N / 2 + 255) / 256, 256>>>(
        accb, ST5, 8, b_h1, H1_N, h1, H1_N, H1_N);
    gemm_bf16_kernel<<<dim3(H2_N / BN, B_SZ / BM, 8), 256, GEMM_SMEM>>>(
        h1, H1_N, Wm6, H2_N, nullptr, 0, b_h2, H2_N, 128, H1_N, accb, ST6, H2_N, 0, 0);
    reduce_bias_relu_kernel<<<(B_SZ * H2_N / 2 + 255) / 256, 256>>>(
        accb, ST6, 8, b_h2, H2_N, h2, H2_N, H2_N);
    final_kernel<<<B_SZ / 8, 256>>>(h2, W_out, b_out, y);
}

// round 10
// speedup vs baseline: 1.1790x; 1.1790x over previous
#include <cuda_runtime.h>
#include <cuda_bf16.h>
#include <cstdint>

typedef __nv_bfloat16 bf16;

// ---------------- problem dims ----------------
#define B_SZ   512
#define NSNP   20000
#define NGEN   5000
#define NPRO   3000
#define IN_COLS 28000     // NPRO + NGEN + NSNP
#define H1_N   1024
#define H2_N   256

// padded dims
#define NG_P   5120
#define NP_P   3072
#define K2_P   5024
#define K3_P   8192       // bridge K = 5120 + 3072
#define K4_P   3008
#define K5_P   6144       // fuse K = 3072 + 3072

// GEMM1 K-chunks (mult of 32; first small to cut serial mask exposure)
#define KC0 2496
#define KC1 5824
#define KC2 5824
#define KC3 5856

// ---------------- device scratch ----------------
__device__ bf16 g_snp[(size_t)B_SZ * NSNP];
__device__ bf16 g_gen[(size_t)B_SZ * K2_P];
__device__ bf16 g_pro[(size_t)B_SZ * K4_P];
__device__ bf16 g_Wm1[(size_t)NSNP * NG_P];   // [k][n]
__device__ bf16 g_Wm2[(size_t)K2_P * NP_P];
__device__ bf16 g_Wm3[(size_t)K3_P * NP_P];
__device__ bf16 g_Wm4[(size_t)K4_P * NP_P];
__device__ bf16 g_Wm5[(size_t)K5_P * H1_N];
__device__ bf16 g_Wm6[(size_t)H1_N * H2_N];
__device__ bf16 g_bridge[(size_t)B_SZ * K3_P];
__device__ bf16 g_fuse[(size_t)B_SZ * K5_P];
__device__ bf16 g_h1[(size_t)B_SZ * H1_N];
__device__ bf16 g_h2[(size_t)B_SZ * H2_N];
__device__ float g_accbuf[(size_t)8 * B_SZ * NG_P];   // split-K slice accumulators

// ---------------- helpers ----------------
__device__ __forceinline__ uint32_t smem_u32(const void* p) {
    return (uint32_t)__cvta_generic_to_shared(p);
}
__device__ __forceinline__ void cp_async16(uint32_t saddr, const void* gaddr) {
    asm volatile("cp.async.cg.shared.global [%0], [%1], 16;\n" ::"r"(saddr), "l"(gaddr));
}
__device__ __forceinline__ void cp_async_commit() {
    asm volatile("cp.async.commit_group;\n" ::: "memory");
}
template <int N>
__device__ __forceinline__ void cp_async_wait() {
    asm volatile("cp.async.wait_group %0;\n" ::"n"(N) : "memory");
}

// ---------------- mask + transpose + bf16 convert ----------------
__global__ void mask_transpose_kernel(const float* __restrict__ W, int ldw,
                                      const float* __restrict__ adj, int lda,
                                      bf16* __restrict__ out, int ldo,
                                      int K, int N) {
    __shared__ float sW[64][33];
    const int k0 = blockIdx.y * 32;
    const int n0 = blockIdx.x * 64;
    const int lin = threadIdx.y * 32 + threadIdx.x;

    {
        const int rn = lin >> 2, seg = (lin & 3) * 8;
        const int gn = n0 + rn;
        const int gk = k0 + seg;
        if (gn < N && gk + 7 < K) {
            const float4 v0 = *(const float4*)&W[(size_t)gn * ldw + gk];
            const float4 v1 = *(const float4*)&W[(size_t)gn * ldw + gk + 4];
            sW[rn][seg + 0] = v0.x; sW[rn][seg + 1] = v0.y;
            sW[rn][seg + 2] = v0.z; sW[rn][seg + 3] = v0.w;
            sW[rn][seg + 4] = v1.x; sW[rn][seg + 5] = v1.y;
            sW[rn][seg + 6] = v1.z; sW[rn][seg + 7] = v1.w;
        } else {
#pragma unroll
            for (int i = 0; i < 8; i++)
                sW[rn][seg + i] = (gn < N && gk + i < K) ? W[(size_t)gn * ldw + gk + i] : 0.f;
        }
    }
    __syncthreads();

    const int kl = lin >> 3;
    const int nb = (lin & 7) * 8;
    const int gk = k0 + kl;
    float v[8];
    if (gk < K && n0 + nb + 7 < N) {
        if (adj != nullptr) {
            const float4 a0 = *(const float4*)&adj[(size_t)gk * lda + n0 + nb];
            const float4 a1 = *(const float4*)&adj[(size_t)gk * lda + n0 + nb + 4];
            v[0] = sW[nb + 0][kl] * a0.x; v[1] = sW[nb + 1][kl] * a0.y;
            v[2] = sW[nb + 2][kl] * a0.z; v[3] = sW[nb + 3][kl] * a0.w;
            v[4] = sW[nb + 4][kl] * a1.x; v[5] = sW[nb + 5][kl] * a1.y;
            v[6] = sW[nb + 6][kl] * a1.z; v[7] = sW[nb + 7][kl] * a1.w;
        } else {
#pragma unroll
            for (int i = 0; i < 8; i++) v[i] = sW[nb + i][kl];
        }
    } else {
#pragma unroll
        for (int i = 0; i < 8; i++) {
            const int gn = n0 + nb + i;
            float x = 0.f;
            if (gk < K && gn < N) {
                x = sW[nb + i][kl];
                if (adj != nullptr) x *= adj[(size_t)gk * lda + gn];
            }
            v[i] = x;
        }
    }
    uint4 o;
    __nv_bfloat162 p;
    p = __floats2bfloat162_rn(v[0], v[1]); o.x = *(uint32_t*)&p;
    p = __floats2bfloat162_rn(v[2], v[3]); o.y = *(uint32_t*)&p;
    p = __floats2bfloat162_rn(v[4], v[5]); o.z = *(uint32_t*)&p;
    p = __floats2bfloat162_rn(v[6], v[7]); o.w = *(uint32_t*)&p;
    *(uint4*)&out[(size_t)gk * ldo + n0 + nb] = o;
}

// ---------------- fast activation convert (vectorized, 16B stores) ----------------
__global__ void convert_pad_v_kernel(const float* __restrict__ src, int src_ld,
                                     bf16* __restrict__ dst, int dst_ld,
                                     int nvalid) {
    int c8 = blockIdx.x * blockDim.x + threadIdx.x;
    int col = c8 * 8;
    if (col >= dst_ld) return;
    int r = blockIdx.y;
    uint4 o;
    if (col < nvalid) {
        const float4 v0 = *(const float4*)&src[(size_t)r * src_ld + col];
        const float4 v1 = *(const float4*)&src[(size_t)r * src_ld + col + 4];
        __nv_bfloat162 p;
        p = __floats2bfloat162_rn(v0.x, v0.y); o.x = *(uint32_t*)&p;
        p = __floats2bfloat162_rn(v0.z, v0.w); o.y = *(uint32_t*)&p;
        p = __floats2bfloat162_rn(v1.x, v1.y); o.z = *(uint32_t*)&p;
        p = __floats2bfloat162_rn(v1.z, v1.w); o.w = *(uint32_t*)&p;
    } else {
        o = make_uint4(0, 0, 0, 0);
    }
    *(uint4*)&dst[(size_t)r * dst_ld + col] = o;
}

// ---------------- bf16 GEMM with split-K (round-8 core: 128 thr, 64x64 warp tile) ----------------
// BM=128 BN=128 BK=32, 4 warps (2x2), 3-stage cp.async, 2 CTAs/SM.
// Kz must be mult of 32; slice covers [z*Kz, min((z+1)*Kz, Ktotal)).
#define BM 128
#define BN 128
#define BKG 32
#define AS_LD 40
#define BS_LD 136
#define STAGES 3
#define GEMM_SMEM (STAGES * (BM * AS_LD + BKG * BS_LD) * 2)

__global__ __launch_bounds__(128, 2) void gemm_bf16_kernel(
    const bf16* __restrict__ A, int lda,
    const bf16* __restrict__ Bw, int ldb,
    bf16* __restrict__ C, int ldc,
    const float* __restrict__ bias, int Nreal,
    int Kz, int Ktotal,
    float* __restrict__ Cacc, size_t accStride, int ldacc,
    int load_prev, int store_final) {
    extern __shared__ bf16 smem[];
    bf16* As = smem;                              // [STAGES][BM][AS_LD]
    bf16* Bs = smem + STAGES * BM * AS_LD;        // [STAGES][BKG][BS_LD]

    const int tid = threadIdx.x;
    const int bm = blockIdx.y * BM;
    const int bn = blockIdx.x * BN;
    const int warp = tid >> 5, lane = tid & 31;
    const int wm = (warp & 1) * 64;
    const int wn = (warp >> 1) * 64;

    // K-slice
    const int kbase = blockIdx.z * Kz;
    int Kthis = Ktotal - kbase;
    if (Kthis > Kz) Kthis = Kz;
    const bf16* Az = A + kbase;
    const bf16* Bz = Bw + (size_t)kbase * ldb;
    float* Cacc_z = Cacc + (size_t)blockIdx.z * accStride;

    float acc[4][8][4];
#pragma unroll
    for (int i = 0; i < 4; i++)
#pragma unroll
        for (int j = 0; j < 8; j++)
#pragma unroll
            for (int r = 0; r < 4; r++) acc[i][j][r] = 0.f;

    const int T = Kthis / BKG;
    const int a_row = tid >> 2, a_seg = (tid & 3) * 8;
    const int b_row = tid >> 4, b_seg = (tid & 15) * 8;

#define LOAD_TILE(t, s)                                                              \
    {                                                                                \
        const int k0_ = (t) * BKG;                                                   \
        bf16* as_ = As + (s) * BM * AS_LD;                                           \
        bf16* bs_ = Bs + (s) * BKG * BS_LD;                                          \
        _Pragma("unroll") for (int p = 0; p < 4; p++) {                              \
            const int row = a_row + p * 32;                                          \
            cp_async16(smem_u32(as_ + row * AS_LD + a_seg),                          \
                       Az + (size_t)(bm + row) * lda + k0_ + a_seg);                 \
        }                                                                            \
        _Pragma("unroll") for (int p = 0; p < 4; p++) {                              \
            const int row = b_row + p * 8;                                           \
            cp_async16(smem_u32(bs_ + row * BS_LD + b_seg),                          \
                       Bz + (size_t)(k0_ + row) * ldb + bn + b_seg);                 \
        }                                                                            \
    }

    LOAD_TILE(0, 0);
    cp_async_commit();
    if (T > 1) LOAD_TILE(1, 1);
    cp_async_commit();

    for (int t = 0; t < T; ++t) {
        cp_async_wait<STAGES - 2>();
        __syncthreads();

        if (t + STAGES - 1 < T) LOAD_TILE(t + STAGES - 1, (t + STAGES - 1) % STAGES);
        cp_async_commit();

        const int s = t % STAGES;
        const bf16* as_ = As + s * BM * AS_LD;
        const bf16* bs_ = Bs + s * BKG * BS_LD;
#pragma unroll
        for (int kk = 0; kk < BKG; kk += 16) {
            uint32_t a[4][4];
#pragma unroll
            for (int im = 0; im < 4; im++) {
                uint32_t addr = smem_u32(as_ + (wm + im * 16 + (lane & 15)) * AS_LD + kk + (lane >> 4) * 8);
                asm volatile("ldmatrix.sync.aligned.m8n8.x4.shared.b16 {%0,%1,%2,%3}, [%4];"
                             : "=r"(a[im][0]), "=r"(a[im][1]), "=r"(a[im][2]), "=r"(a[im][3])
                             : "r"(addr));
            }
            uint32_t b[8][2];
#pragma unroll
            for (int ip = 0; ip < 4; ip++) {
                uint32_t r0, r1, r2, r3;
                uint32_t addr = smem_u32(bs_ + (kk + (lane & 15)) * BS_LD + wn + ip * 16 + (lane >> 4) * 8);
                asm volatile("ldmatrix.sync.aligned.m8n8.x4.trans.shared.b16 {%0,%1,%2,%3}, [%4];"
                             : "=r"(r0), "=r"(r1), "=r"(r2), "=r"(r3)
                             : "r"(addr));
                b[ip * 2][0] = r0; b[ip * 2][1] = r1;
                b[ip * 2 + 1][0] = r2; b[ip * 2 + 1][1] = r3;
            }
#pragma unroll
            for (int im = 0; im < 4; im++)
#pragma unroll
                for (int jn = 0; jn < 8; jn++) {
                    asm volatile(
                        "mma.sync.aligned.m16n8k16.row.col.f32.bf16.bf16.f32 "
                        "{%0,%1,%2,%3}, {%4,%5,%6,%7}, {%8,%9}, {%0,%1,%2,%3};"
                        : "+f"(acc[im][jn][0]), "+f"(acc[im][jn][1]),
                          "+f"(acc[im][jn][2]), "+f"(acc[im][jn][3])
                        : "r"(a[im][0]), "r"(a[im][1]), "r"(a[im][2]), "r"(a[im][3]),
                          "r"(b[jn][0]), "r"(b[jn][1]));
                }
        }
        __syncthreads();
    }

    if (!store_final) {
#pragma unroll
        for (int im = 0; im < 4; im++) {
            int r0 = bm + wm + im * 16 + (lane >> 2);
#pragma unroll
            for (int jn = 0; jn < 8; jn++) {
                int col = bn + wn + jn * 8 + (lane & 3) * 2;
                float2* p0 = (float2*)&Cacc_z[(size_t)r0 * ldacc + col];
                float2* p1 = (float2*)&Cacc_z[(size_t)(r0 + 8) * ldacc + col];
                float2 v0 = make_float2(acc[im][jn][0], acc[im][jn][1]);
                float2 v1 = make_float2(acc[im][jn][2], acc[im][jn][3]);
                if (load_prev) {
                    float2 o0 = *p0, o1 = *p1;
                    v0.x += o0.x; v0.y += o0.y;
                    v1.x += o1.x; v1.y += o1.y;
                }
                *p0 = v0; *p1 = v1;
            }
        }
    } else {
#pragma unroll
        for (int im = 0; im < 4; im++) {
            int r0 = bm + wm + im * 16 + (lane >> 2);
#pragma unroll
            for (int jn = 0; jn < 8; jn++) {
                int col = bn + wn + jn * 8 + (lane & 3) * 2;
                float bv0 = (col < Nreal) ? bias[col] : 0.f;
                float bv1 = (col + 1 < Nreal) ? bias[col + 1] : 0.f;
                float f0 = fmaxf(acc[im][jn][0] + bv0, 0.f);
                float f1 = fmaxf(acc[im][jn][1] + bv1, 0.f);
                float f2 = fmaxf(acc[im][jn][2] + bv0, 0.f);
                float f3 = fmaxf(acc[im][jn][3] + bv1, 0.f);
                *(__nv_bfloat162*)&C[(size_t)r0 * ldc + col] = __floats2bfloat162_rn(f0, f1);
                *(__nv_bfloat162*)&C[(size_t)(r0 + 8) * ldc + col] = __floats2bfloat162_rn(f2, f3);
            }
        }
    }
}

// ---------------- split-K reduce: C = relu(sum_s acc[s] + bias) -> bf16 ----------------
__global__ void reduce_bias_relu_kernel(const float* __restrict__ acc, size_t accStride, int S,
                                        const float* __restrict__ bias, int Nreal,
                                        bf16* __restrict__ C, int ldc, int Np) {
    int idx = blockIdx.x * blockDim.x + threadIdx.x;
    int half = Np >> 1;
    int total = B_SZ * half;
    if (idx >= total) return;
    int r = idx / half;
    int col = (idx - r * half) * 2;
    float s0 = 0.f, s1 = 0.f;
    const float* p = acc + (size_t)r * Np + col;
    for (int s = 0; s < S; s++) {
        float2 v = *(const float2*)(p + (size_t)s * accStride);
        s0 += v.x; s1 += v.y;
    }
    s0 += (col < Nreal) ? bias[col] : 0.f;
    s1 += (col + 1 < Nreal) ? bias[col + 1] : 0.f;
    *(__nv_bfloat162*)&C[(size_t)r * ldc + col] =
        __floats2bfloat162_rn(fmaxf(s0, 0.f), fmaxf(s1, 0.f));
}

// ---------------- final: y = sigmoid(h2 @ Wout + bout) ----------------
__global__ void final_kernel(const bf16* __restrict__ h2,
                             const float* __restrict__ Wout,
                             const float* __restrict__ bout,
                             float* __restrict__ y) {
    int row = blockIdx.x * 8 + (threadIdx.x >> 5);
    int lane = threadIdx.x & 31;
    float s = 0.f;
#pragma unroll
    for (int c = lane; c < H2_N; c += 32)
        s += __bfloat162float(h2[(size_t)row * H2_N + c]) * Wout[c];
#pragma unroll
    for (int o = 16; o; o >>= 1) s += __shfl_xor_sync(0xffffffffu, s, o);
    if (lane == 0) y[row] = 1.f / (1.f + expf(-(s + bout[0])));
}

// ---------------- launch ----------------
static inline int align32_half(int k) { return ((k / 2) + 31) & ~31; }

extern "C" void kernel_launch(void* const* d_in, const int* in_sizes, int n_in,
                              void* d_out, int out_size) {
    (void)in_sizes; (void)n_in; (void)out_size;
    const float* in_mat = (const float*)d_in[0];
    const float* adj_sg = (const float*)d_in[1];
    const float* adj_gp = (const float*)d_in[2];
    const float* adj_br = (const float*)d_in[3];
    const float* adj_pp = (const float*)d_in[4];
    const float* W_sg = (const float*)d_in[5];
    const float* b_sg = (const float*)d_in[6];
    const float* W_gp = (const float*)d_in[7];
    const float* b_gp = (const float*)d_in[8];
    const float* W_br = (const float*)d_in[9];
    const float* b_br = (const float*)d_in[10];
    const float* W_pp = (const float*)d_in[11];
    const float* b_pp = (const float*)d_in[12];
    const float* W_h1 = (const float*)d_in[13];
    const float* b_h1 = (const float*)d_in[14];
    const float* W_h2 = (const float*)d_in[15];
    const float* b_h2 = (const float*)d_in[16];
    const float* W_out = (const float*)d_in[17];
    const float* b_out = (const float*)d_in[18];
    float* y = (float*)d_out;

    bf16 *snp, *gen, *pro, *Wm1, *Wm2, *Wm3, *Wm4, *Wm5, *Wm6, *bridge, *fuse, *h1, *h2;
    float* accb;
    cudaGetSymbolAddress((void**)&snp, g_snp);
    cudaGetSymbolAddress((void**)&gen, g_gen);
    cudaGetSymbolAddress((void**)&pro, g_pro);
    cudaGetSymbolAddress((void**)&Wm1, g_Wm1);
    cudaGetSymbolAddress((void**)&Wm2, g_Wm2);
    cudaGetSymbolAddress((void**)&Wm3, g_Wm3);
    cudaGetSymbolAddress((void**)&Wm4, g_Wm4);
    cudaGetSymbolAddress((void**)&Wm5, g_Wm5);
    cudaGetSymbolAddress((void**)&Wm6, g_Wm6);
    cudaGetSymbolAddress((void**)&bridge, g_bridge);
    cudaGetSymbolAddress((void**)&fuse, g_fuse);
    cudaGetSymbolAddress((void**)&h1, g_h1);
    cudaGetSymbolAddress((void**)&h2, g_h2);
    cudaGetSymbolAddress((void**)&accb, g_accbuf);

    cudaFuncSetAttribute(gemm_bf16_kernel, cudaFuncAttributeMaxDynamicSharedMemorySize, GEMM_SMEM);

    static cudaStream_t s1 = nullptr;
    static cudaEvent_t ev_fork = nullptr, ev_join = nullptr;
    static cudaEvent_t ev_m1 = nullptr, ev_m2 = nullptr, ev_m3 = nullptr;
    if (s1 == nullptr) {
        cudaStreamCreateWithFlags(&s1, cudaStreamNonBlocking);
        cudaEventCreateWithFlags(&ev_fork, cudaEventDisableTiming);
        cudaEventCreateWithFlags(&ev_join, cudaEventDisableTiming);
        cudaEventCreateWithFlags(&ev_m1, cudaEventDisableTiming);
        cudaEventCreateWithFlags(&ev_m2, cudaEventDisableTiming);
        cudaEventCreateWithFlags(&ev_m3, cudaEventDisableTiming);
    }

    dim3 mt(32, 8);
    const int kc_off[4] = {0, KC0, KC0 + KC1, KC0 + KC1 + KC2};
    const int kc_len[4] = {KC0, KC1, KC2, KC3};
    const size_t ST1 = (size_t)B_SZ * NG_P;
    const size_t ST3 = (size_t)B_SZ * NP_P;
    const size_t ST5 = (size_t)B_SZ * H1_N;
    const size_t ST6 = (size_t)B_SZ * H2_N;

    // ======== s0: critical path start ========
    convert_pad_v_kernel<<<dim3((NSNP / 8 + 255) / 256, B_SZ), 256>>>(
        in_mat + NPRO + NGEN, IN_COLS, snp, NSNP, NSNP);
    mask_transpose_kernel<<<dim3(NG_P / 64, kc_len[0] / 32), mt>>>(
        W_sg + kc_off[0], NSNP, adj_sg + (size_t)kc_off[0] * NGEN, NGEN,
        Wm1 + (size_t)kc_off[0] * NG_P, NG_P, kc_len[0], NGEN);
    cudaEventRecord(ev_fork, 0);
    cudaStreamWaitEvent(s1, ev_fork, 0);

    // ======== s1: mask chunks 1-3 + side prep + GEMM2/GEMM4 ========
    mask_transpose_kernel<<<dim3(NG_P / 64, kc_len[1] / 32), mt, 0, s1>>>(
        W_sg + kc_off[1], NSNP, adj_sg + (size_t)kc_off[1] * NGEN, NGEN,
        Wm1 + (size_t)kc_off[1] * NG_P, NG_P, kc_len[1], NGEN);
    cudaEventRecord(ev_m1, s1);
    mask_transpose_kernel<<<dim3(NG_P / 64, kc_len[2] / 32), mt, 0, s1>>>(
        W_sg + kc_off[2], NSNP, adj_sg + (size_t)kc_off[2] * NGEN, NGEN,
        Wm1 + (size_t)kc_off[2] * NG_P, NG_P, kc_len[2], NGEN);
    cudaEventRecord(ev_m2, s1);
    mask_transpose_kernel<<<dim3(NG_P / 64, kc_len[3] / 32), mt, 0, s1>>>(
        W_sg + kc_off[3], NSNP, adj_sg + (size_t)kc_off[3] * NGEN, NGEN,
        Wm1 + (size_t)kc_off[3] * NG_P, NG_P, kc_len[3], NGEN);
    cudaEventRecord(ev_m3, s1);

    // ======== s0: GEMM1 chunks, split-K=2 each (Kz aligned up to 32) ========
    gemm_bf16_kernel<<<dim3(NG_P / BN, B_SZ / BM, 2), 128, GEMM_SMEM>>>(
        snp + kc_off[0], NSNP, Wm1 + (size_t)kc_off[0] * NG_P, NG_P,
        nullptr, 0, b_sg, NGEN, align32_half(kc_len[0]), kc_len[0], accb, ST1, NG_P, 0, 0);
    cudaStreamWaitEvent(0, ev_m1, 0);
    gemm_bf16_kernel<<<dim3(NG_P / BN, B_SZ / BM, 2), 128, GEMM_SMEM>>>(
        snp + kc_off[1], NSNP, Wm1 + (size_t)kc_off[1] * NG_P, NG_P,
        nullptr, 0, b_sg, NGEN, align32_half(kc_len[1]), kc_len[1], accb, ST1, NG_P, 1, 0);
    cudaStreamWaitEvent(0, ev_m2, 0);
    gemm_bf16_kernel<<<dim3(NG_P / BN, B_SZ / BM, 2), 128, GEMM_SMEM>>>(
        snp + kc_off[2], NSNP, Wm1 + (size_t)kc_off[2] * NG_P, NG_P,
        nullptr, 0, b_sg, NGEN, align32_half(kc_len[2]), kc_len[2], accb, ST1, NG_P, 1, 0);
    cudaStreamWaitEvent(0, ev_m3, 0);
    gemm_bf16_kernel<<<dim3(NG_P / BN, B_SZ / BM, 2), 128, GEMM_SMEM>>>(
        snp + kc_off[3], NSNP, Wm1 + (size_t)kc_off[3] * NG_P, NG_P,
        nullptr, 0, b_sg, NGEN, align32_half(kc_len[3]), kc_len[3], accb, ST1, NG_P, 1, 0);
    reduce_bias_relu_kernel<<<(B_SZ * NG_P / 2 + 255) / 256, 256>>>(
        accb, ST1, 2, b_sg, NGEN, bridge, K3_P, NG_P);

    // ======== s1 (continued): side prep + GEMM2/GEMM4 ========
    convert_pad_v_kernel<<<dim3((K2_P / 8 + 255) / 256, B_SZ), 256, 0, s1>>>(
        in_mat + NPRO, IN_COLS, gen, K2_P, NGEN);
    convert_pad_v_kernel<<<dim3((K4_P / 8 + 255) / 256, B_SZ), 256, 0, s1>>>(
        in_mat, IN_COLS, pro, K4_P, NPRO);
    mask_transpose_kernel<<<dim3(NP_P / 64, K2_P / 32), mt, 0, s1>>>(W_gp, NGEN, adj_gp, NPRO, Wm2, NP_P, NGEN, NPRO);
    mask_transpose_kernel<<<dim3(NP_P / 64, NG_P / 32), mt, 0, s1>>>(W_br, NGEN + NPRO, adj_br, NPRO, Wm3, NP_P, NGEN, NPRO);
    mask_transpose_kernel<<<dim3(NP_P / 64, NP_P / 32), mt, 0, s1>>>(W_br + NGEN, NGEN + NPRO,
                                                                    adj_br + (size_t)NGEN * NPRO, NPRO,
                                                                    Wm3 + (size_t)NG_P * NP_P, NP_P, NPRO, NPRO);
    mask_transpose_kernel<<<dim3(NP_P / 64, K4_P / 32), mt, 0, s1>>>(W_pp, NPRO, adj_pp, NPRO, Wm4, NP_P, NPRO, NPRO);
    mask_transpose_kernel<<<dim3(H1_N / 64, NP_P / 32), mt, 0, s1>>>(W_h1, 2 * NPRO, nullptr, 0, Wm5, H1_N, NPRO, H1_N);
    mask_transpose_kernel<<<dim3(H1_N / 64, NP_P / 32), mt, 0, s1>>>(W_h1 + NPRO, 2 * NPRO, nullptr, 0,
                                                                    Wm5 + (size_t)NP_P * H1_N, H1_N, NPRO, H1_N);
    mask_transpose_kernel<<<dim3(H2_N / 64, H1_N / 32), mt, 0, s1>>>(W_h2, H1_N, nullptr, 0, Wm6, H2_N, H1_N, H2_N);
    gemm_bf16_kernel<<<dim3(NP_P / BN, B_SZ / BM, 1), 128, GEMM_SMEM, s1>>>(
        gen, K2_P, Wm2, NP_P, bridge + NG_P, K3_P, b_gp, NPRO, K2_P, K2_P, nullptr, 0, 0, 0, 1);
    gemm_bf16_kernel<<<dim3(NP_P / BN, B_SZ / BM, 1), 128, GEMM_SMEM, s1>>>(
        pro, K4_P, Wm4, NP_P, fuse + NP_P, K5_P, b_pp, NPRO, K4_P, K4_P, nullptr, 0, 0, 0, 1);
    cudaEventRecord(ev_join, s1);

    // ======== s0: join, dependent tail (split-K) ========
    cudaStreamWaitEvent(0, ev_join, 0);
    gemm_bf16_kernel<<<dim3(NP_P / BN, B_SZ / BM, 3), 128, GEMM_SMEM>>>(
        bridge, K3_P, Wm3, NP_P, nullptr, 0, b_br, NPRO, 2752, K3_P, accb, ST3, NP_P, 0, 0);
    reduce_bias_relu_kernel<<<(B_SZ * NP_P / 2 + 255) / 256, 256>>>(
        accb, ST3, 3, b_br, NPRO, fuse, K5_P, NP_P);
    gemm_bf16_kernel<<<dim3(H1_N / BN, B_SZ / BM, 8), 128, GEMM_SMEM>>>(
        fuse, K5_P, Wm5, H1_N, nullptr, 0, b_h1, H1_N, 768, K5_P, accb, ST5, H1_N, 0, 0);
    reduce_bias_relu_kernel<<<(B_SZ * H1_N / 2 + 255) / 256, 256>>>(
        accb, ST5, 8, b_h1, H1_N, h1, H1_N, H1_N);
    gemm_bf16_kernel<<<dim3(H2_N / BN, B_SZ / BM, 8), 128, GEMM_SMEM>>>(
        h1, H1_N, Wm6, H2_N, nullptr, 0, b_h2, H2_N, 128, H1_N, accb, ST6, H2_N, 0, 0);
    reduce_bias_relu_kernel<<<(B_SZ * H2_N / 2 + 255) / 256, 256>>>(
        accb, ST6, 8, b_h2, H2_N, h2, H2_N, H2_N);
    final_kernel<<<B_SZ / 8, 256>>>(h2, W_out, b_out, y);
}